// round 13
// baseline (speedup 1.0000x reference)
#include <cuda_runtime.h>
#include <math.h>

#define PAD 68
#define ARR (64 * PAD)
#define SMEM_FLOATS (2 * ARR + 32)
#define SMEM_BYTES (SMEM_FLOATS * 4)

typedef unsigned long long u64;

// column-softmaxed weights, o-major: g_wT[o*64 + i] = w[i][o]
__device__ float g_wT[64 * 64];

static __device__ __forceinline__ u64 ffma2(u64 a, u64 b, u64 c) {
    u64 d; asm("fma.rn.f32x2 %0,%1,%2,%3;" : "=l"(d) : "l"(a), "l"(b), "l"(c)); return d;
}
static __device__ __forceinline__ u64 fmul2(u64 a, u64 b) {
    u64 d; asm("mul.rn.f32x2 %0,%1,%2;" : "=l"(d) : "l"(a), "l"(b)); return d;
}
static __device__ __forceinline__ float hadd2(u64 v) {
    float lo, hi; asm("mov.b64 {%0,%1},%2;" : "=f"(lo), "=f"(hi) : "l"(v));
    return lo + hi;
}
static __device__ __forceinline__ void unpack2(u64 v, float& lo, float& hi) {
    asm("mov.b64 {%0,%1},%2;" : "=f"(lo), "=f"(hi) : "l"(v));
}
static __device__ __forceinline__ u64 bcast2(float f) {
    u64 d; asm("mov.b64 %0,{%1,%1};" : "=l"(d) : "f"(f)); return d;
}

// acos via A&S 4.4.45 7-term poly, Estrin form: abs err ~2e-8 on [-1,1]
// Input pre-clamped to |x| <= 1-1e-7, so om >= 1e-7 (rsqrt safe).
static __device__ __forceinline__ float acos_fast(float x) {
    float ax = fabsf(x);
    float om = 1.0f - ax;
    float s = om * rsqrtf(om);   // sqrt(1-ax), MUFU issued early
    float x2 = ax * ax;
    float x4 = x2 * x2;
    float p01 = fmaf(ax, -0.2145988016f, 1.5707963050f);
    float p23 = fmaf(ax, -0.0501743046f, 0.0889789874f);
    float p45 = fmaf(ax, -0.0170881256f, 0.0308918810f);
    float p67 = fmaf(ax, -0.0012624911f, 0.0066700901f);
    float q0 = fmaf(p23, x2, p01);
    float q1 = fmaf(p67, x2, p45);
    float p = fmaf(q1, x4, q0);
    float r = p * s;
    return (x < 0.0f) ? 3.14159265358979f - r : r;
}

__global__ void wprep_kernel(const float* __restrict__ wraw) {
    int o = threadIdx.x;  // 64 threads, one output column each
    float s = 0.f;
    #pragma unroll 8
    for (int i = 0; i < 64; ++i) s += expf(wraw[i * 64 + o]);
    float inv = 1.0f / s;
    #pragma unroll 8
    for (int i = 0; i < 64; ++i) g_wT[o * 64 + i] = expf(wraw[i * 64 + o]) * inv;
}

__global__ __launch_bounds__(128, 5) void mfd_kernel(const float* __restrict__ xg,
                                                     float* __restrict__ out) {
    extern __shared__ float sm[];
    float* Xs = sm;              // [64][PAD]  x rows (dd-contiguous), read-only
    float* Ws = Xs + ARR;        // [64][PAD]  A (iter input) / F (mid-iter), warp-owned rows

    const int n   = blockIdx.x;
    const int tid = threadIdx.x;
    const int oc  = tid >> 4;    // 0..7  (warp = {2w, 2w+1} oc values)
    const int ic  = tid & 15;    // 0..15
    const int dq  = 4 * ic;      // this thread's dd-quad base

    // ---- load x tile (coalesced float4) ----
    const float* xn = xg + (size_t)n * 4096;
    for (int t = tid; t < 1024; t += 128) {
        float4 v = ((const float4*)xn)[t];
        int r = t >> 4, c = (t & 15) << 2;
        *(float4*)&Xs[r * PAD + c] = v;
    }
    __syncthreads();

    // ---- persistent a quads in registers: a_o = x_0 for all o ----
    ulonglong2 x0q = *(const ulonglong2*)&Xs[dq];
    u64 aq0[8], aq1[8];
    #pragma unroll
    for (int k = 0; k < 8; ++k) { aq0[k] = x0q.x; aq1[k] = x0q.y; }

    // Unit-norm inputs; exp-map preserves unit norm: ||v||^2 = 1 - dc^2.
    // Warps own their Ws rows (o = oc + 8k) -> warp-local sync inside loop.
    const float HI = 1.0f - 1e-7f;

    #pragma unroll 1
    for (int it = 0; it < 3; ++it) {
        float corr[8];

        if (it == 0) {
            // ===== iter-0: D[o][i] = x0 . x_i for ALL o -> 4 direct dots =====
            u64 dp2[4];
            #pragma unroll
            for (int j = 0; j < 4; ++j) dp2[j] = 0ull;
            #pragma unroll 4
            for (int dd = 0; dd < 64; dd += 4) {
                ulonglong2 x0p = *(const ulonglong2*)&Xs[dd];  // row 0, broadcast
                #pragma unroll
                for (int j = 0; j < 4; ++j) {
                    ulonglong2 xp = *(const ulonglong2*)&Xs[(ic + 16 * j) * PAD + dd];
                    dp2[j] = ffma2(x0p.x, xp.x, dp2[j]);
                    dp2[j] = ffma2(x0p.y, xp.y, dp2[j]);
                }
            }
            float dcv[4], ffv[4];
            #pragma unroll
            for (int j = 0; j < 4; ++j) {
                float draw = hadd2(dp2[j]);
                float dc   = fminf(fmaxf(draw, -HI), HI);
                dcv[j] = dc;
                ffv[j] = acos_fast(dc) * rsqrtf(fmaf(-dc, dc, 1.0f));
            }
            #pragma unroll
            for (int k = 0; k < 8; ++k) {
                int o = oc + 8 * k;
                float cr = 0.f;
                #pragma unroll
                for (int j = 0; j < 4; ++j) {
                    int i = ic + 16 * j;
                    float F = g_wT[o * 64 + i] * ffv[j];
                    Ws[o * PAD + i] = F;
                    cr = fmaf(F, dcv[j], cr);
                }
                corr[k] = cr;
            }
        } else {
            // ===== GEMM1 in two k-passes; F-phase interleaved per pass.
            // Pass p's F-writes touch rows {oc+8k, k in p*4..p*4+3}, disjoint
            // from the A-rows the other pass reads. Warp-private rows.
            #pragma unroll
            for (int pass = 0; pass < 2; ++pass) {
                u64 acc2[4][4];
                #pragma unroll
                for (int kk = 0; kk < 4; ++kk)
                    #pragma unroll
                    for (int j = 0; j < 4; ++j) acc2[kk][j] = 0ull;

                #pragma unroll 4
                for (int dd = 0; dd < 64; dd += 4) {
                    ulonglong2 xp[4];
                    #pragma unroll
                    for (int j = 0; j < 4; ++j)
                        xp[j] = *(const ulonglong2*)&Xs[(ic + 16 * j) * PAD + dd];
                    #pragma unroll
                    for (int kk = 0; kk < 4; ++kk) {
                        ulonglong2 ap = *(const ulonglong2*)
                            &Ws[(oc + 8 * (pass * 4 + kk)) * PAD + dd];
                        #pragma unroll
                        for (int j = 0; j < 4; ++j) {
                            acc2[kk][j] = ffma2(ap.x, xp[j].x, acc2[kk][j]);
                            acc2[kk][j] = ffma2(ap.y, xp[j].y, acc2[kk][j]);
                        }
                    }
                }

                // F-phase for this pass's k
                #pragma unroll
                for (int kk = 0; kk < 4; ++kk) {
                    int k = pass * 4 + kk;
                    int o = oc + 8 * k;
                    float cr = 0.f;
                    #pragma unroll
                    for (int j = 0; j < 4; ++j) {
                        int i = ic + 16 * j;
                        float draw  = hadd2(acc2[kk][j]);
                        float dc    = fminf(fmaxf(draw, -HI), HI);
                        float theta = acos_fast(dc);
                        float nv2   = fmaf(-dc, dc, 1.0f);
                        float f     = theta * rsqrtf(nv2);
                        float F     = g_wT[o * 64 + i] * f;
                        Ws[o * PAD + i] = F;
                        cr = fmaf(F, dc, cr);
                    }
                    corr[k] = cr;
                }
            }
        }
        __syncwarp();  // warp's F rows complete in Ws

        // ===== GEMM2 (f32x2, F broadcast): G[o][dd] over thread's dd-quad
        u64 g20[8], g21[8];
        #pragma unroll
        for (int k = 0; k < 8; ++k) { g20[k] = 0ull; g21[k] = 0ull; }

        #pragma unroll 4
        for (int i4 = 0; i4 < 64; i4 += 4) {
            ulonglong2 xq[4];
            #pragma unroll
            for (int r = 0; r < 4; ++r)
                xq[r] = *(const ulonglong2*)&Xs[(i4 + r) * PAD + dq];
            #pragma unroll
            for (int k = 0; k < 8; ++k) {
                ulonglong2 fp = *(const ulonglong2*)&Ws[(oc + 8 * k) * PAD + i4];
                float f0, f1, f2, f3;
                unpack2(fp.x, f0, f1);
                unpack2(fp.y, f2, f3);
                u64 b0 = bcast2(f0), b1 = bcast2(f1), b2 = bcast2(f2), b3 = bcast2(f3);
                g20[k] = ffma2(b0, xq[0].x, g20[k]);
                g20[k] = ffma2(b1, xq[1].x, g20[k]);
                g20[k] = ffma2(b2, xq[2].x, g20[k]);
                g20[k] = ffma2(b3, xq[3].x, g20[k]);
                g21[k] = ffma2(b0, xq[0].y, g21[k]);
                g21[k] = ffma2(b1, xq[1].y, g21[k]);
                g21[k] = ffma2(b2, xq[2].y, g21[k]);
                g21[k] = ffma2(b3, xq[3].y, g21[k]);
            }
        }

        // corr reduction deferred here: SHFL latency overlapped GEMM2 issue
        #pragma unroll
        for (int k = 0; k < 8; ++k) {
            #pragma unroll
            for (int s = 1; s < 16; s <<= 1)
                corr[k] += __shfl_xor_sync(0xffffffffu, corr[k], s);
        }

        // ===== exp-map update (a in registers) =====
        #pragma unroll
        for (int k = 0; k < 8; ++k) {
            int o = oc + 8 * k;
            u64 ncb = bcast2(-corr[k]);
            u64 gr0 = ffma2(ncb, aq0[k], g20[k]);
            u64 gr1 = ffma2(ncb, aq1[k], g21[k]);
            float q0, q1, q2, q3;
            unpack2(gr0, q0, q1);
            unpack2(gr1, q2, q3);
            float gn2 = q0 * q0;
            gn2 = fmaf(q1, q1, gn2);
            gn2 = fmaf(q2, q2, gn2);
            gn2 = fmaf(q3, q3, gn2);
            #pragma unroll
            for (int s = 1; s < 16; s <<= 1)
                gn2 += __shfl_xor_sync(0xffffffffu, gn2, s);
            float inv = rsqrtf(fmaxf(gn2, 1e-30f));
            float gn = gn2 * inv;                 // sqrt(gn2)
            float sg, cg;
            __sincosf(gn, &sg, &cg);
            float sc = (gn2 < 1e-14f) ? 1.0f : sg * inv;
            if (gn2 < 1e-14f) cg = 1.0f;

            u64 cgb = bcast2(cg), scb = bcast2(sc);
            u64 an0 = ffma2(cgb, aq0[k], fmul2(scb, gr0));
            u64 an1 = ffma2(cgb, aq1[k], fmul2(scb, gr1));

            if (it == 2) {
                ulonglong2 ov; ov.x = an0; ov.y = an1;
                *(ulonglong2*)&out[(size_t)n * 4096 + o * 64 + dq] = ov;
            } else {
                aq0[k] = an0; aq1[k] = an1;
                ulonglong2 av; av.x = an0; av.y = an1;
                *(ulonglong2*)&Ws[o * PAD + dq] = av;   // A for next iter's GEMM1
            }
        }
        __syncwarp();  // warp's A rows ready for its next iteration
    }
}

extern "C" void kernel_launch(void* const* d_in, const int* in_sizes, int n_in,
                              void* d_out, int out_size) {
    const float* x    = (const float*)d_in[0];   // (4,256,64,64)
    const float* wraw = (const float*)d_in[1];   // (64,64)
    float* out = (float*)d_out;                  // (4,256,64,64)

    cudaFuncSetAttribute(mfd_kernel, cudaFuncAttributeMaxDynamicSharedMemorySize, SMEM_BYTES);

    wprep_kernel<<<1, 64>>>(wraw);
    mfd_kernel<<<1024, 128, SMEM_BYTES>>>(x, out);
}